// round 4
// baseline (speedup 1.0000x reference)
#include <cuda_runtime.h>

#define NBLK 888            // 148 SMs x 6 resident CTAs: exactly one wave
#define NTHR 256

// Per-block partial sums (deterministic reduction, no data atomics).
__device__ float g_part_p[NBLK];
__device__ float g_part_ll[NBLK];
__device__ float g_part_np[NBLK];
__device__ unsigned g_ticket = 0;   // self-resetting last-block-done counter

__device__ __forceinline__ float frcp(float x) {
    float y;
    asm("rcp.approx.f32 %0, %1;" : "=f"(y) : "f"(x));
    return y;
}

struct Acc { float p, ll, np; };

// One mixture component's binned probability: sigmoid(xu') - sigmoid(xl')
// rewritten as (el - eu) / ((1+eu)(1+el)), eu = exp((m-t-HB)/s), el = exp((m-t+HB)/s).
// Saturation: eu/el overflow -> denominator inf -> rcp = 0 -> product 0 or NaN,
// and fmaxf(NaN, EPS) = EPS, matching the reference's clamp in that regime.
__device__ __forceinline__ float comp_prob(float d /* m - t */, float s) {
    const float EPS = 1e-8f;
    const float HB  = 0.05f;   // HALF_BIN
    float inv = frcp(s + EPS);
    float eu  = __expf((d - HB) * inv);
    float el  = __expf((d + HB) * inv);
    float num = el - eu;
    float den = frcp((1.f + eu) * (1.f + el));
    return fmaxf(num * den, EPS);
}

__device__ __forceinline__ void process_elem(
    float p, float t,
    float m0, float s0, float w0,
    float m1, float s1, float w1,
    float m2, float s2, float w2,
    Acc& a)
{
    const float EPS = 1e-8f;

    float lik = w0 * comp_prob(m0 - t, s0)
              + w1 * comp_prob(m1 - t, s1)
              + w2 * comp_prob(m2 - t, s2);

    bool paid = (t > 0.f);
    float ll = __logf(lik + EPS);
    if (paid) { a.ll += ll; a.np += 1.f; }

    // target*log(p) + (1-target)*log(1-p) == log(paid ? p : 1-p); clip >= -100
    float q = paid ? p : (1.f - p);
    a.p -= fmaxf(__logf(q), -100.f);
}

__global__ void __launch_bounds__(NTHR, 6) zimol_fused(
    const float* __restrict__ pp, const float* __restrict__ mu,
    const float* __restrict__ sg, const float* __restrict__ wt,
    const float* __restrict__ tv, float* __restrict__ out, int B)
{
    const int nvec = B >> 2;            // float4 vectors per row
    Acc a = {0.f, 0.f, 0.f};

    const float4* pp4 = reinterpret_cast<const float4*>(pp);
    const float4* tv4 = reinterpret_cast<const float4*>(tv);
    const float4* mu4 = reinterpret_cast<const float4*>(mu);
    const float4* sg4 = reinterpret_cast<const float4*>(sg);
    const float4* wt4 = reinterpret_cast<const float4*>(wt);

    for (int v = blockIdx.x * NTHR + threadIdx.x; v < nvec; v += NBLK * NTHR) {
        float4 p4 = __ldg(pp4 + v);
        float4 t4 = __ldg(tv4 + v);
        float4 m[3], s[3], w[3];
        #pragma unroll
        for (int k = 0; k < 3; k++) {
            m[k] = __ldg(mu4 + k * nvec + v);
            s[k] = __ldg(sg4 + k * nvec + v);
            w[k] = __ldg(wt4 + k * nvec + v);
        }
        process_elem(p4.x, t4.x, m[0].x, s[0].x, w[0].x,
                     m[1].x, s[1].x, w[1].x, m[2].x, s[2].x, w[2].x, a);
        process_elem(p4.y, t4.y, m[0].y, s[0].y, w[0].y,
                     m[1].y, s[1].y, w[1].y, m[2].y, s[2].y, w[2].y, a);
        process_elem(p4.z, t4.z, m[0].z, s[0].z, w[0].z,
                     m[1].z, s[1].z, w[1].z, m[2].z, s[2].z, w[2].z, a);
        process_elem(p4.w, t4.w, m[0].w, s[0].w, w[0].w,
                     m[1].w, s[1].w, w[1].w, m[2].w, s[2].w, w[2].w, a);
    }

    // Scalar tail (B not divisible by 4) — robustness; no-op for B = 4M.
    int tail = B & 3;
    if (tail) {
        int base = nvec << 2;
        int i = blockIdx.x * NTHR + threadIdx.x;
        if (i < tail) {
            int idx = base + i;
            process_elem(pp[idx], tv[idx],
                         mu[0 * B + idx], sg[0 * B + idx], wt[0 * B + idx],
                         mu[1 * B + idx], sg[1 * B + idx], wt[1 * B + idx],
                         mu[2 * B + idx], sg[2 * B + idx], wt[2 * B + idx], a);
        }
    }

    // ---- Block reduction (all float, shuffle + tiny smem) ----
    #pragma unroll
    for (int o = 16; o > 0; o >>= 1) {
        a.p  += __shfl_down_sync(0xffffffffu, a.p,  o);
        a.ll += __shfl_down_sync(0xffffffffu, a.ll, o);
        a.np += __shfl_down_sync(0xffffffffu, a.np, o);
    }

    __shared__ float shp[8], shl[8], shn[8];
    __shared__ bool s_last;
    int wid  = threadIdx.x >> 5;
    int lane = threadIdx.x & 31;
    if (lane == 0) { shp[wid] = a.p; shl[wid] = a.ll; shn[wid] = a.np; }
    __syncthreads();

    if (threadIdx.x == 0) {
        float vp = 0.f, vl = 0.f, vn = 0.f;
        #pragma unroll
        for (int i = 0; i < 8; i++) { vp += shp[i]; vl += shl[i]; vn += shn[i]; }
        g_part_p[blockIdx.x]  = vp;
        g_part_ll[blockIdx.x] = vl;
        g_part_np[blockIdx.x] = vn;
        __threadfence();
        unsigned t = atomicAdd(&g_ticket, 1u);
        s_last = (t == (unsigned)(NBLK - 1));
        if (s_last) g_ticket = 0u;   // self-reset: deterministic across replays
    }
    __syncthreads();

    // ---- Last block finalizes (float, 888 partials) ----
    if (s_last) {
        float sp = 0.f, sl = 0.f, sn = 0.f;
        for (int i = threadIdx.x; i < NBLK; i += NTHR) {
            sp += g_part_p[i];
            sl += g_part_ll[i];
            sn += g_part_np[i];
        }
        #pragma unroll
        for (int o = 16; o > 0; o >>= 1) {
            sp += __shfl_down_sync(0xffffffffu, sp, o);
            sl += __shfl_down_sync(0xffffffffu, sl, o);
            sn += __shfl_down_sync(0xffffffffu, sn, o);
        }
        if (lane == 0) { shp[wid] = sp; shl[wid] = sl; shn[wid] = sn; }
        __syncthreads();
        if (threadIdx.x == 0) {
            float vp = 0.f, vl = 0.f, vn = 0.f;
            #pragma unroll
            for (int i = 0; i < 8; i++) { vp += shp[i]; vl += shl[i]; vn += shn[i]; }
            float purchase = vp / (float)B;
            float ltv = (vn > 0.f) ? -(vl / fmaxf(vn, 1.f)) : 0.f;
            out[0] = purchase + ltv;
        }
    }
}

extern "C" void kernel_launch(void* const* d_in, const int* in_sizes, int n_in,
                              void* d_out, int out_size)
{
    const float* pp = (const float*)d_in[0];  // predicted_purchase_prob (B,)
    const float* mu = (const float*)d_in[1];  // mu     (K,B)
    const float* sg = (const float*)d_in[2];  // sigma  (K,B)
    const float* wt = (const float*)d_in[3];  // weight (K,B)
    const float* tv = (const float*)d_in[4];  // true_values (B,)
    int B = in_sizes[0];

    zimol_fused<<<NBLK, NTHR>>>(pp, mu, sg, wt, tv, (float*)d_out, B);
}

// round 5
// speedup vs baseline: 1.0008x; 1.0008x over previous
#include <cuda_runtime.h>

#define NBLK 1480           // 148 SMs x 5 resident x 2 waves (work-steal rebalancing)
#define NTHR 256

// Per-block partial sums (deterministic reduction, no data atomics).
__device__ float g_part_p[NBLK];
__device__ float g_part_ll[NBLK];
__device__ float g_part_np[NBLK];
__device__ unsigned g_ticket = 0;   // self-resetting last-block-done counter

__device__ __forceinline__ float frcp(float x) {
    float y;
    asm("rcp.approx.f32 %0, %1;" : "=f"(y) : "f"(x));
    return y;
}

__device__ __forceinline__ float4 ldcs4(const float4* p) {
    return __ldcs(p);   // streaming: evict-first, single-touch data
}

struct Acc { float p, ll, np; };

// One scalar element: mirrors the reference formula exactly (including the
// unstable sigmoid-difference + max(.,EPS) clamp behavior in float32).
__device__ __forceinline__ void process_elem(
    float p, float t,
    float m0, float s0, float w0,
    float m1, float s1, float w1,
    float m2, float s2, float w2,
    Acc& a)
{
    const float EPS = 1e-8f;
    const float HB  = 0.05f;   // HALF_BIN

    float lik = 0.f;
    {
        float inv = frcp(s0 + EPS);
        float su  = frcp(1.f + __expf(-((t + HB - m0) * inv)));
        float sl  = frcp(1.f + __expf(-((t - HB - m0) * inv)));
        lik += w0 * fmaxf(su - sl, EPS);
    }
    {
        float inv = frcp(s1 + EPS);
        float su  = frcp(1.f + __expf(-((t + HB - m1) * inv)));
        float sl  = frcp(1.f + __expf(-((t - HB - m1) * inv)));
        lik += w1 * fmaxf(su - sl, EPS);
    }
    {
        float inv = frcp(s2 + EPS);
        float su  = frcp(1.f + __expf(-((t + HB - m2) * inv)));
        float sl  = frcp(1.f + __expf(-((t - HB - m2) * inv)));
        lik += w2 * fmaxf(su - sl, EPS);
    }

    bool paid = (t > 0.f);
    float ll = __logf(lik + EPS);
    if (paid) { a.ll += ll; a.np += 1.f; }

    // target*log(p) + (1-target)*log(1-p) == log(paid ? p : 1-p); clip >= -100
    float q = paid ? p : (1.f - p);
    a.p -= fmaxf(__logf(q), -100.f);
}

__global__ void __launch_bounds__(NTHR, 5) zimol_fused(
    const float* __restrict__ pp, const float* __restrict__ mu,
    const float* __restrict__ sg, const float* __restrict__ wt,
    const float* __restrict__ tv, float* __restrict__ out, int B)
{
    const int nvec = B >> 2;            // float4 vectors per row
    Acc a = {0.f, 0.f, 0.f};

    const float4* pp4 = reinterpret_cast<const float4*>(pp);
    const float4* tv4 = reinterpret_cast<const float4*>(tv);
    const float4* mu4 = reinterpret_cast<const float4*>(mu);
    const float4* sg4 = reinterpret_cast<const float4*>(sg);
    const float4* wt4 = reinterpret_cast<const float4*>(wt);

    for (int v = blockIdx.x * NTHR + threadIdx.x; v < nvec; v += NBLK * NTHR) {
        float4 p4 = ldcs4(pp4 + v);
        float4 t4 = ldcs4(tv4 + v);
        float4 m[3], s[3], w[3];
        #pragma unroll
        for (int k = 0; k < 3; k++) {
            m[k] = ldcs4(mu4 + k * nvec + v);
            s[k] = ldcs4(sg4 + k * nvec + v);
            w[k] = ldcs4(wt4 + k * nvec + v);
        }
        process_elem(p4.x, t4.x, m[0].x, s[0].x, w[0].x,
                     m[1].x, s[1].x, w[1].x, m[2].x, s[2].x, w[2].x, a);
        process_elem(p4.y, t4.y, m[0].y, s[0].y, w[0].y,
                     m[1].y, s[1].y, w[1].y, m[2].y, s[2].y, w[2].y, a);
        process_elem(p4.z, t4.z, m[0].z, s[0].z, w[0].z,
                     m[1].z, s[1].z, w[1].z, m[2].z, s[2].z, w[2].z, a);
        process_elem(p4.w, t4.w, m[0].w, s[0].w, w[0].w,
                     m[1].w, s[1].w, w[1].w, m[2].w, s[2].w, w[2].w, a);
    }

    // Scalar tail (B not divisible by 4) — robustness; no-op for B = 4M.
    int tail = B & 3;
    if (tail) {
        int base = nvec << 2;
        int i = blockIdx.x * NTHR + threadIdx.x;
        if (i < tail) {
            int idx = base + i;
            process_elem(pp[idx], tv[idx],
                         mu[0 * B + idx], sg[0 * B + idx], wt[0 * B + idx],
                         mu[1 * B + idx], sg[1 * B + idx], wt[1 * B + idx],
                         mu[2 * B + idx], sg[2 * B + idx], wt[2 * B + idx], a);
        }
    }

    // ---- Block reduction (all float, shuffle + tiny smem) ----
    #pragma unroll
    for (int o = 16; o > 0; o >>= 1) {
        a.p  += __shfl_down_sync(0xffffffffu, a.p,  o);
        a.ll += __shfl_down_sync(0xffffffffu, a.ll, o);
        a.np += __shfl_down_sync(0xffffffffu, a.np, o);
    }

    __shared__ float shp[8], shl[8], shn[8];
    __shared__ bool s_last;
    int wid  = threadIdx.x >> 5;
    int lane = threadIdx.x & 31;
    if (lane == 0) { shp[wid] = a.p; shl[wid] = a.ll; shn[wid] = a.np; }
    __syncthreads();

    if (threadIdx.x == 0) {
        float vp = 0.f, vl = 0.f, vn = 0.f;
        #pragma unroll
        for (int i = 0; i < 8; i++) { vp += shp[i]; vl += shl[i]; vn += shn[i]; }
        g_part_p[blockIdx.x]  = vp;
        g_part_ll[blockIdx.x] = vl;
        g_part_np[blockIdx.x] = vn;
        __threadfence();
        unsigned t = atomicAdd(&g_ticket, 1u);
        s_last = (t == (unsigned)(NBLK - 1));
        if (s_last) g_ticket = 0u;   // self-reset: deterministic across replays
    }
    __syncthreads();

    // ---- Last block finalizes (float, 1480 partials) ----
    if (s_last) {
        float sp = 0.f, sl = 0.f, sn = 0.f;
        for (int i = threadIdx.x; i < NBLK; i += NTHR) {
            sp += g_part_p[i];
            sl += g_part_ll[i];
            sn += g_part_np[i];
        }
        #pragma unroll
        for (int o = 16; o > 0; o >>= 1) {
            sp += __shfl_down_sync(0xffffffffu, sp, o);
            sl += __shfl_down_sync(0xffffffffu, sl, o);
            sn += __shfl_down_sync(0xffffffffu, sn, o);
        }
        if (lane == 0) { shp[wid] = sp; shl[wid] = sl; shn[wid] = sn; }
        __syncthreads();
        if (threadIdx.x == 0) {
            float vp = 0.f, vl = 0.f, vn = 0.f;
            #pragma unroll
            for (int i = 0; i < 8; i++) { vp += shp[i]; vl += shl[i]; vn += shn[i]; }
            float purchase = vp / (float)B;
            float ltv = (vn > 0.f) ? -(vl / fmaxf(vn, 1.f)) : 0.f;
            out[0] = purchase + ltv;
        }
    }
}

extern "C" void kernel_launch(void* const* d_in, const int* in_sizes, int n_in,
                              void* d_out, int out_size)
{
    const float* pp = (const float*)d_in[0];  // predicted_purchase_prob (B,)
    const float* mu = (const float*)d_in[1];  // mu     (K,B)
    const float* sg = (const float*)d_in[2];  // sigma  (K,B)
    const float* wt = (const float*)d_in[3];  // weight (K,B)
    const float* tv = (const float*)d_in[4];  // true_values (B,)
    int B = in_sizes[0];

    zimol_fused<<<NBLK, NTHR>>>(pp, mu, sg, wt, tv, (float*)d_out, B);
}

// round 6
// speedup vs baseline: 1.0284x; 1.0275x over previous
#include <cuda_runtime.h>

#define NBLK 740            // 148 SMs x 5 resident CTAs: exactly one wave
#define NTHR 256

// Per-block partial sums (deterministic reduction, no data atomics).
__device__ float g_part_p[NBLK];
__device__ float g_part_ll[NBLK];
__device__ float g_part_np[NBLK];
__device__ unsigned g_ticket = 0;   // self-resetting last-block-done counter

__device__ __forceinline__ float frcp(float x) {
    float y;
    asm("rcp.approx.f32 %0, %1;" : "=f"(y) : "f"(x));
    return y;
}
__device__ __forceinline__ float fex2(float x) {
    float y;
    asm("ex2.approx.f32 %0, %1;" : "=f"(y) : "f"(x));
    return y;
}

struct Acc { float p, ll, np; };

// Binned mixture probability, log2-domain, instruction-minimized:
//   sigmoid(u)-sigmoid(l) = (el - eu) / ((1+eu)(1+el)),
//   eu = 2^(a-b), el = 2^(a+b), a = (m-t)*inv*log2e, b = HB*inv*log2e.
// Saturation: overflow -> den=inf -> rcp=0 -> product 0/NaN; fmax(.,EPS)=EPS,
// matching the reference's clamped regime.
__device__ __forceinline__ float comp_prob(float m, float t, float s) {
    const float EPS = 1e-8f;
    const float HB  = 0.05f;                       // HALF_BIN
    const float L2E = 1.4426950408889634f;         // log2(e)
    float il = frcp(s + EPS) * L2E;
    float a  = (m - t) * il;
    float b  = HB * il;
    float eu = fex2(a - b);
    float el = fex2(a + b);
    float den = frcp((1.f + eu) * (1.f + el));
    return fmaxf((el - eu) * den, EPS);
}

__device__ __forceinline__ void process_elem(
    float p, float t,
    float m0, float s0, float w0,
    float m1, float s1, float w1,
    float m2, float s2, float w2,
    Acc& a)
{
    const float EPS = 1e-8f;

    float lik = w0 * comp_prob(m0, t, s0);
    lik = fmaf(w1, comp_prob(m1, t, s1), lik);
    lik = fmaf(w2, comp_prob(m2, t, s2), lik);

    bool paid = (t > 0.f);
    float ll = __logf(lik + EPS);
    if (paid) { a.ll += ll; a.np += 1.f; }

    // target*log(p) + (1-target)*log(1-p) == log(paid ? p : 1-p); clip >= -100
    float q = paid ? p : (1.f - p);
    a.p -= fmaxf(__logf(q), -100.f);
}

__global__ void __launch_bounds__(NTHR, 5) zimol_fused(
    const float* __restrict__ pp, const float* __restrict__ mu,
    const float* __restrict__ sg, const float* __restrict__ wt,
    const float* __restrict__ tv, float* __restrict__ out, int B)
{
    const int nvec = B >> 2;            // float4 vectors per row
    Acc a = {0.f, 0.f, 0.f};

    const float4* pp4 = reinterpret_cast<const float4*>(pp);
    const float4* tv4 = reinterpret_cast<const float4*>(tv);
    const float4* mu4 = reinterpret_cast<const float4*>(mu);
    const float4* sg4 = reinterpret_cast<const float4*>(sg);
    const float4* wt4 = reinterpret_cast<const float4*>(wt);

    for (int v = blockIdx.x * NTHR + threadIdx.x; v < nvec; v += NBLK * NTHR) {
        float4 p4 = __ldg(pp4 + v);
        float4 t4 = __ldg(tv4 + v);
        float4 m[3], s[3], w[3];
        #pragma unroll
        for (int k = 0; k < 3; k++) {
            m[k] = __ldg(mu4 + k * nvec + v);
            s[k] = __ldg(sg4 + k * nvec + v);
            w[k] = __ldg(wt4 + k * nvec + v);
        }
        process_elem(p4.x, t4.x, m[0].x, s[0].x, w[0].x,
                     m[1].x, s[1].x, w[1].x, m[2].x, s[2].x, w[2].x, a);
        process_elem(p4.y, t4.y, m[0].y, s[0].y, w[0].y,
                     m[1].y, s[1].y, w[1].y, m[2].y, s[2].y, w[2].y, a);
        process_elem(p4.z, t4.z, m[0].z, s[0].z, w[0].z,
                     m[1].z, s[1].z, w[1].z, m[2].z, s[2].z, w[2].z, a);
        process_elem(p4.w, t4.w, m[0].w, s[0].w, w[0].w,
                     m[1].w, s[1].w, w[1].w, m[2].w, s[2].w, w[2].w, a);
    }

    // Scalar tail (B not divisible by 4) — robustness; no-op for B = 4M.
    int tail = B & 3;
    if (tail) {
        int base = nvec << 2;
        int i = blockIdx.x * NTHR + threadIdx.x;
        if (i < tail) {
            int idx = base + i;
            process_elem(pp[idx], tv[idx],
                         mu[0 * B + idx], sg[0 * B + idx], wt[0 * B + idx],
                         mu[1 * B + idx], sg[1 * B + idx], wt[1 * B + idx],
                         mu[2 * B + idx], sg[2 * B + idx], wt[2 * B + idx], a);
        }
    }

    // ---- Block reduction (all float, shuffle + tiny smem) ----
    #pragma unroll
    for (int o = 16; o > 0; o >>= 1) {
        a.p  += __shfl_down_sync(0xffffffffu, a.p,  o);
        a.ll += __shfl_down_sync(0xffffffffu, a.ll, o);
        a.np += __shfl_down_sync(0xffffffffu, a.np, o);
    }

    __shared__ float shp[8], shl[8], shn[8];
    __shared__ bool s_last;
    int wid  = threadIdx.x >> 5;
    int lane = threadIdx.x & 31;
    if (lane == 0) { shp[wid] = a.p; shl[wid] = a.ll; shn[wid] = a.np; }
    __syncthreads();

    if (threadIdx.x == 0) {
        float vp = 0.f, vl = 0.f, vn = 0.f;
        #pragma unroll
        for (int i = 0; i < 8; i++) { vp += shp[i]; vl += shl[i]; vn += shn[i]; }
        g_part_p[blockIdx.x]  = vp;
        g_part_ll[blockIdx.x] = vl;
        g_part_np[blockIdx.x] = vn;
        __threadfence();
        unsigned t = atomicAdd(&g_ticket, 1u);
        s_last = (t == (unsigned)(NBLK - 1));
        if (s_last) g_ticket = 0u;   // self-reset: deterministic across replays
    }
    __syncthreads();

    // ---- Last block finalizes (float, 740 partials) ----
    if (s_last) {
        float sp = 0.f, sl = 0.f, sn = 0.f;
        for (int i = threadIdx.x; i < NBLK; i += NTHR) {
            sp += g_part_p[i];
            sl += g_part_ll[i];
            sn += g_part_np[i];
        }
        #pragma unroll
        for (int o = 16; o > 0; o >>= 1) {
            sp += __shfl_down_sync(0xffffffffu, sp, o);
            sl += __shfl_down_sync(0xffffffffu, sl, o);
            sn += __shfl_down_sync(0xffffffffu, sn, o);
        }
        if (lane == 0) { shp[wid] = sp; shl[wid] = sl; shn[wid] = sn; }
        __syncthreads();
        if (threadIdx.x == 0) {
            float vp = 0.f, vl = 0.f, vn = 0.f;
            #pragma unroll
            for (int i = 0; i < 8; i++) { vp += shp[i]; vl += shl[i]; vn += shn[i]; }
            float purchase = vp / (float)B;
            float ltv = (vn > 0.f) ? -(vl / fmaxf(vn, 1.f)) : 0.f;
            out[0] = purchase + ltv;
        }
    }
}

extern "C" void kernel_launch(void* const* d_in, const int* in_sizes, int n_in,
                              void* d_out, int out_size)
{
    const float* pp = (const float*)d_in[0];  // predicted_purchase_prob (B,)
    const float* mu = (const float*)d_in[1];  // mu     (K,B)
    const float* sg = (const float*)d_in[2];  // sigma  (K,B)
    const float* wt = (const float*)d_in[3];  // weight (K,B)
    const float* tv = (const float*)d_in[4];  // true_values (B,)
    int B = in_sizes[0];

    zimol_fused<<<NBLK, NTHR>>>(pp, mu, sg, wt, tv, (float*)d_out, B);
}

// round 7
// speedup vs baseline: 1.1219x; 1.0910x over previous
#include <cuda_runtime.h>

#define NBLK 296            // 148 SMs x 2 resident CTAs: exactly one wave
#define NTHR 256
#define STRIDE (NBLK * NTHR)

// Per-block partial sums (deterministic reduction, no data atomics).
__device__ float g_part_p[NBLK];
__device__ float g_part_ll[NBLK];
__device__ float g_part_np[NBLK];
__device__ unsigned g_ticket = 0;   // self-resetting last-block-done counter

__device__ __forceinline__ float frcp(float x) {
    float y;
    asm("rcp.approx.f32 %0, %1;" : "=f"(y) : "f"(x));
    return y;
}
__device__ __forceinline__ float fex2(float x) {
    float y;
    asm("ex2.approx.f32 %0, %1;" : "=f"(y) : "f"(x));
    return y;
}

struct Acc { float p, ll, np; };

// Full iteration payload: 11 float4s (p, t, 3x{m,s,w}).
struct V11 {
    float4 p, t;
    float4 m0, m1, m2;
    float4 s0, s1, s2;
    float4 w0, w1, w2;
};

// Binned mixture probability, log2-domain:
//   sigmoid(u)-sigmoid(l) = (el-eu)/((1+eu)(1+el)),
//   eu = 2^(a-b), el = 2^(a+b), a=(m-t)*inv*log2e, b=HB*inv*log2e.
// Saturation: overflow -> den inf -> rcp 0 -> 0/NaN; fmax(.,EPS)=EPS,
// matching the reference's clamped regime.
__device__ __forceinline__ float comp_prob(float m, float t, float s) {
    const float EPS = 1e-8f;
    const float HB  = 0.05f;
    const float L2E = 1.4426950408889634f;
    float il = frcp(s + EPS) * L2E;
    float a  = (m - t) * il;
    float b  = HB * il;
    float eu = fex2(a - b);
    float el = fex2(a + b);
    float den = frcp((1.f + eu) * (1.f + el));
    return fmaxf((el - eu) * den, EPS);
}

__device__ __forceinline__ void process_elem(
    float p, float t,
    float m0, float s0, float w0,
    float m1, float s1, float w1,
    float m2, float s2, float w2,
    Acc& a)
{
    const float EPS = 1e-8f;

    float lik = w0 * comp_prob(m0, t, s0);
    lik = fmaf(w1, comp_prob(m1, t, s1), lik);
    lik = fmaf(w2, comp_prob(m2, t, s2), lik);

    bool paid = (t > 0.f);
    float ll = __logf(lik + EPS);
    if (paid) { a.ll += ll; a.np += 1.f; }

    float q = paid ? p : (1.f - p);
    a.p -= fmaxf(__logf(q), -100.f);
}

__device__ __forceinline__ void load_v11(
    V11& b, int v, int nvec,
    const float4* __restrict__ pp4, const float4* __restrict__ tv4,
    const float4* __restrict__ mu4, const float4* __restrict__ sg4,
    const float4* __restrict__ wt4)
{
    b.p  = __ldg(pp4 + v);
    b.t  = __ldg(tv4 + v);
    b.m0 = __ldg(mu4 + v);
    b.m1 = __ldg(mu4 + nvec + v);
    b.m2 = __ldg(mu4 + 2 * nvec + v);
    b.s0 = __ldg(sg4 + v);
    b.s1 = __ldg(sg4 + nvec + v);
    b.s2 = __ldg(sg4 + 2 * nvec + v);
    b.w0 = __ldg(wt4 + v);
    b.w1 = __ldg(wt4 + nvec + v);
    b.w2 = __ldg(wt4 + 2 * nvec + v);
}

__device__ __forceinline__ void compute_v11(const V11& b, Acc& a)
{
    process_elem(b.p.x, b.t.x, b.m0.x, b.s0.x, b.w0.x,
                 b.m1.x, b.s1.x, b.w1.x, b.m2.x, b.s2.x, b.w2.x, a);
    process_elem(b.p.y, b.t.y, b.m0.y, b.s0.y, b.w0.y,
                 b.m1.y, b.s1.y, b.w1.y, b.m2.y, b.s2.y, b.w2.y, a);
    process_elem(b.p.z, b.t.z, b.m0.z, b.s0.z, b.w0.z,
                 b.m1.z, b.s1.z, b.w1.z, b.m2.z, b.s2.z, b.w2.z, a);
    process_elem(b.p.w, b.t.w, b.m0.w, b.s0.w, b.w0.w,
                 b.m1.w, b.s1.w, b.w1.w, b.m2.w, b.s2.w, b.w2.w, a);
}

__global__ void __launch_bounds__(NTHR, 2) zimol_fused(
    const float* __restrict__ pp, const float* __restrict__ mu,
    const float* __restrict__ sg, const float* __restrict__ wt,
    const float* __restrict__ tv, float* __restrict__ out, int B)
{
    const int nvec = B >> 2;
    Acc a = {0.f, 0.f, 0.f};

    const float4* pp4 = reinterpret_cast<const float4*>(pp);
    const float4* tv4 = reinterpret_cast<const float4*>(tv);
    const float4* mu4 = reinterpret_cast<const float4*>(mu);
    const float4* sg4 = reinterpret_cast<const float4*>(sg);
    const float4* wt4 = reinterpret_cast<const float4*>(wt);

    const int idx = blockIdx.x * NTHR + threadIdx.x;
    // number of grid-stride iterations for this thread
    int n = (idx < nvec) ? (nvec - idx + STRIDE - 1) / STRIDE : 0;

    V11 bufA, bufB;
    if (n > 0) load_v11(bufA, idx, nvec, pp4, tv4, mu4, sg4, wt4);

    // Software pipeline: prefetch iteration i+1 while computing iteration i.
    int i = 0;
    #pragma unroll 2
    for (; i + 1 < n; i++) {
        int vn = idx + (i + 1) * STRIDE;
        if (i & 1) {
            load_v11(bufA, vn, nvec, pp4, tv4, mu4, sg4, wt4);
            compute_v11(bufB, a);
        } else {
            load_v11(bufB, vn, nvec, pp4, tv4, mu4, sg4, wt4);
            compute_v11(bufA, a);
        }
    }
    if (n > 0) {
        if (i & 1) compute_v11(bufB, a);
        else       compute_v11(bufA, a);
    }

    // Scalar tail (B not divisible by 4) — robustness; no-op for B = 4M.
    int tail = B & 3;
    if (tail) {
        int base = nvec << 2;
        if (idx < tail) {
            int j = base + idx;
            process_elem(pp[j], tv[j],
                         mu[0 * B + j], sg[0 * B + j], wt[0 * B + j],
                         mu[1 * B + j], sg[1 * B + j], wt[1 * B + j],
                         mu[2 * B + j], sg[2 * B + j], wt[2 * B + j], a);
        }
    }

    // ---- Block reduction (all float, shuffle + tiny smem) ----
    #pragma unroll
    for (int o = 16; o > 0; o >>= 1) {
        a.p  += __shfl_down_sync(0xffffffffu, a.p,  o);
        a.ll += __shfl_down_sync(0xffffffffu, a.ll, o);
        a.np += __shfl_down_sync(0xffffffffu, a.np, o);
    }

    __shared__ float shp[8], shl[8], shn[8];
    __shared__ bool s_last;
    int wid  = threadIdx.x >> 5;
    int lane = threadIdx.x & 31;
    if (lane == 0) { shp[wid] = a.p; shl[wid] = a.ll; shn[wid] = a.np; }
    __syncthreads();

    if (threadIdx.x == 0) {
        float vp = 0.f, vl = 0.f, vn = 0.f;
        #pragma unroll
        for (int k = 0; k < 8; k++) { vp += shp[k]; vl += shl[k]; vn += shn[k]; }
        g_part_p[blockIdx.x]  = vp;
        g_part_ll[blockIdx.x] = vl;
        g_part_np[blockIdx.x] = vn;
        __threadfence();
        unsigned t = atomicAdd(&g_ticket, 1u);
        s_last = (t == (unsigned)(NBLK - 1));
        if (s_last) g_ticket = 0u;   // self-reset: deterministic across replays
    }
    __syncthreads();

    // ---- Last block finalizes (float, 296 partials) ----
    if (s_last) {
        float sp = 0.f, sl = 0.f, sn = 0.f;
        for (int k = threadIdx.x; k < NBLK; k += NTHR) {
            sp += g_part_p[k];
            sl += g_part_ll[k];
            sn += g_part_np[k];
        }
        #pragma unroll
        for (int o = 16; o > 0; o >>= 1) {
            sp += __shfl_down_sync(0xffffffffu, sp, o);
            sl += __shfl_down_sync(0xffffffffu, sl, o);
            sn += __shfl_down_sync(0xffffffffu, sn, o);
        }
        if (lane == 0) { shp[wid] = sp; shl[wid] = sl; shn[wid] = sn; }
        __syncthreads();
        if (threadIdx.x == 0) {
            float vp = 0.f, vl = 0.f, vn = 0.f;
            #pragma unroll
            for (int k = 0; k < 8; k++) { vp += shp[k]; vl += shl[k]; vn += shn[k]; }
            float purchase = vp / (float)B;
            float ltv = (vn > 0.f) ? -(vl / fmaxf(vn, 1.f)) : 0.f;
            out[0] = purchase + ltv;
        }
    }
}

extern "C" void kernel_launch(void* const* d_in, const int* in_sizes, int n_in,
                              void* d_out, int out_size)
{
    const float* pp = (const float*)d_in[0];  // predicted_purchase_prob (B,)
    const float* mu = (const float*)d_in[1];  // mu     (K,B)
    const float* sg = (const float*)d_in[2];  // sigma  (K,B)
    const float* wt = (const float*)d_in[3];  // weight (K,B)
    const float* tv = (const float*)d_in[4];  // true_values (B,)
    int B = in_sizes[0];

    zimol_fused<<<NBLK, NTHR>>>(pp, mu, sg, wt, tv, (float*)d_out, B);
}